// round 16
// baseline (speedup 1.0000x reference)
#include <cuda_runtime.h>
#include <cuda_fp16.h>
#include <math.h>

#define BB 32
#define TT 512
#define DD 1024
#define VOCAB 50257
#define SS 16
#define BT (BB*TT)
#define H2 2048

// ---------------- scratch (static device globals; no allocation) ----------------
// RULE: device globals are ONLY referenced inside device code. Passing them as
// kernel arguments from host code silently breaks on GB300 (ATS host-shadow).
__device__ unsigned g_aF16[(size_t)BT * DD / 2];    // embed[seq] fp16 A-frags  32 MB
__device__ unsigned g_actF16[(size_t)BT * H2 / 2];  // relu(ff1) fp16 A-frags   64 MB
__device__ unsigned g_w1F16[(size_t)DD * H2 / 2];   // W1 fp16 B-frags           4 MB
__device__ unsigned g_w2F16[(size_t)H2 * DD / 2];   // W2 fp16 B-frags           4 MB
__device__ float g_x[(size_t)BT * DD];              // h + ff                   64 MB
__device__ float g_hidden[(size_t)BT * DD];         // LN output                64 MB
__device__ float g_slot[BT];
__device__ float g_wbar[DD];
__device__ float g_query[BB * DD];
__device__ float g_mem[BB * SS * DD];
__device__ float g_dl[(size_t)BB * VOCAB];          // query logits
__device__ float g_cl[(size_t)BB * VOCAB];          // ctxattn logits
__device__ float g_use[BB];
__device__ float g_q[BB * DD];
__device__ float g_ctx[BB * DD];                    // pure attention context

__device__ __forceinline__ float warp_sum(float v) {
#pragma unroll
    for (int o = 16; o > 0; o >>= 1) v += __shfl_xor_sync(0xffffffffu, v, o);
    return v;
}
__device__ __forceinline__ unsigned f2tf(float x) {
    unsigned u;
    asm("cvt.rna.tf32.f32 %0, %1;" : "=r"(u) : "f"(x));
    return u;
}
__device__ __forceinline__ unsigned pkf(float lo, float hi) {
    return ((unsigned)__half_as_ushort(__float2half_rn(hi)) << 16) |
           (unsigned)__half_as_ushort(__float2half_rn(lo));
}
__device__ __forceinline__ unsigned pkh(__half lo, __half hi) {
    return ((unsigned)__half_as_ushort(hi) << 16) | (unsigned)__half_as_ushort(lo);
}
__device__ __forceinline__ void mma_f16(float* c,
    unsigned a0, unsigned a1, unsigned a2, unsigned a3,
    unsigned b0, unsigned b1) {
    asm volatile(
        "mma.sync.aligned.m16n8k16.row.col.f32.f16.f16.f32 "
        "{%0,%1,%2,%3}, {%4,%5,%6,%7}, {%8,%9}, {%0,%1,%2,%3};"
        : "+f"(c[0]), "+f"(c[1]), "+f"(c[2]), "+f"(c[3])
        : "r"(a0), "r"(a1), "r"(a2), "r"(a3), "r"(b0), "r"(b1));
}
__device__ __forceinline__ void mma_tf32(float* c,
    unsigned a0, unsigned a1, unsigned a2, unsigned a3,
    unsigned b0, unsigned b1) {
    asm volatile(
        "mma.sync.aligned.m16n8k8.row.col.f32.tf32.tf32.f32 "
        "{%0,%1,%2,%3}, {%4,%5,%6,%7}, {%8,%9}, {%0,%1,%2,%3};"
        : "+f"(c[0]), "+f"(c[1]), "+f"(c[2]), "+f"(c[3])
        : "r"(a0), "r"(a1), "r"(a2), "r"(a3), "r"(b0), "r"(b1));
}
__device__ __forceinline__ unsigned sptr(const void* p) {
    return (unsigned)__cvta_generic_to_shared(p);
}
#define CPA16(dst_u32, src_ptr) \
    asm volatile("cp.async.cg.shared.global [%0], [%1], 16;" :: "r"(dst_u32), "l"(src_ptr))
#define CPA_COMMIT() asm volatile("cp.async.commit_group;")
#define CPA_WAIT1()  asm volatile("cp.async.wait_group 1;")
#define CPA_WAIT0()  asm volatile("cp.async.wait_group 0;")

// fp16 fragment-major stages
#define ASTG 8192
#define BSTG 8192
#define STGB (ASTG + BSTG)
#define NSTAGE 3
#define GSMEM_G 67584           // max(3*STGB=48K, gemm2 epilogue 128*132*4B=67.6K)

// vlogits tf32 smem constants
#define APAD 36
#define BPAD 136
#define VASZ (64 * APAD)                    // fused: 64 A rows
#define VBSZ (32 * BPAD)
#define GSMEM_V (2 * (VASZ + VBSZ) * 4)     // 53248 B (dynamic, opt-in)

// ---------------- K0: wbar = mean_s wg_w ----------------
__global__ void wbar_kernel(const float* __restrict__ wg_w) {
    int d = blockIdx.x * blockDim.x + threadIdx.x;
    if (d < DD) {
        float s = 0.f;
#pragma unroll
        for (int j = 0; j < SS; j++) s += wg_w[d * SS + j];
        g_wbar[d] = s * (1.f / 16.f);
    }
}

// ---------------- prep: W1 [DD][H2] -> fp16 B-fragments (KB1 = 64) ----------------
__global__ __launch_bounds__(256) void prep_w1(const float* __restrict__ W) {
    const int gtid = blockIdx.x * 256 + threadIdx.x;
    const int lane = gtid & 31;
    const int kblk = (gtid >> 5) & 63;
    const int nblk = gtid >> 11;
    const int gid = lane >> 2, tg = lane & 3;
    const int k = kblk * 16 + 2 * tg;
    const int n = nblk * 8 + gid;
    uint2 o;
    o.x = pkf(W[(size_t)k * H2 + n],       W[(size_t)(k + 1) * H2 + n]);
    o.y = pkf(W[(size_t)(k + 8) * H2 + n], W[(size_t)(k + 9) * H2 + n]);
    *(uint2*)(g_w1F16 + (size_t)gtid * 2) = o;
}
// ---------------- prep: W2 [H2][DD] -> fp16 B-fragments (KB2 = 128) ----------------
__global__ __launch_bounds__(256) void prep_w2(const float* __restrict__ W) {
    const int gtid = blockIdx.x * 256 + threadIdx.x;
    const int lane = gtid & 31;
    const int kblk = (gtid >> 5) & 127;
    const int nblk = gtid >> 12;
    const int gid = lane >> 2, tg = lane & 3;
    const int k = kblk * 16 + 2 * tg;
    const int n = nblk * 8 + gid;
    uint2 o;
    o.x = pkf(W[(size_t)k * DD + n],       W[(size_t)(k + 1) * DD + n]);
    o.y = pkf(W[(size_t)(k + 8) * DD + n], W[(size_t)(k + 9) * DD + n]);
    *(uint2*)(g_w2F16 + (size_t)gtid * 2) = o;
}

// ---------------- prep: embed[seq] -> fp16 A-fragments (KB = 64) ----------------
#define PADW 1032
__global__ __launch_bounds__(256) void prep_a(const int* __restrict__ seq,
                                              const float* __restrict__ embed) {
    extern __shared__ __half sA[];   // [16][PADW]
    __shared__ int srow[16];
    const int tid = threadIdx.x;
    const int mblk = blockIdx.x;
    if (tid < 16) srow[tid] = seq[mblk * 16 + tid] * DD;
    __syncthreads();
#pragma unroll
    for (int l = 0; l < 16; l++) {
        int idx = tid + l * 256;
        int r = idx >> 8, c4 = idx & 255;
        float4 v = *(const float4*)(embed + (size_t)srow[r] + c4 * 4);
        __half* p = sA + r * PADW + c4 * 4;
        p[0] = __float2half_rn(v.x); p[1] = __float2half_rn(v.y);
        p[2] = __float2half_rn(v.z); p[3] = __float2half_rn(v.w);
    }
    __syncthreads();
#pragma unroll
    for (int l = 0; l < 8; l++) {
        int c = tid + l * 256;
        int kblk = c >> 5, lane = c & 31;
        int gid = lane >> 2, tg = lane & 3;
        int col = kblk * 16 + 2 * tg;
        uint4 o;
        o.x = pkh(sA[gid * PADW + col],           sA[gid * PADW + col + 1]);
        o.y = pkh(sA[(gid + 8) * PADW + col],     sA[(gid + 8) * PADW + col + 1]);
        o.z = pkh(sA[gid * PADW + col + 8],       sA[gid * PADW + col + 9]);
        o.w = pkh(sA[(gid + 8) * PADW + col + 8], sA[(gid + 8) * PADW + col + 9]);
        *(uint4*)(g_aF16 + (((size_t)mblk * 64 + kblk) * 32 + lane) * 4) = o;
    }
}

// fragment load + fp16 mma step macros
#define LOADF(buf, ks) do {                                                     \
        _Pragma("unroll")                                                       \
        for (int mi = 0; mi < 4; mi++)                                          \
            af[buf][mi] = *(const uint4*)(stg + ((am + mi) * 2 + (ks)) * 512 + lane * 16); \
        _Pragma("unroll")                                                       \
        for (int ni = 0; ni < 4; ni++)                                          \
            bf[buf][ni] = *(const uint2*)(stg + ASTG + ((bn + ni) * 2 + (ks)) * 256 + lane * 8); \
    } while (0)
#define MMAS(buf) do {                                                          \
        _Pragma("unroll")                                                       \
        for (int mi = 0; mi < 4; mi++)                                          \
        _Pragma("unroll")                                                       \
        for (int ni = 0; ni < 4; ni++)                                          \
            mma_f16(acc[mi][ni],                                                \
                    af[buf][mi].x, af[buf][mi].y, af[buf][mi].z, af[buf][mi].w, \
                    bf[buf][ni].x, bf[buf][ni].y);                              \
    } while (0)

// ---------------- gemm1: g_actF16 = Afrag(fp16(relu(h @ W1 + b1))) ----------------
__global__ __launch_bounds__(256) void gemm1_kernel(const float* __restrict__ b1) {
    extern __shared__ unsigned char dsm[];
    __shared__ float sbias[128];
    const int tid = threadIdx.x, warp = tid >> 5, lane = tid & 31;
    const int gid = lane >> 2, tg = lane & 3;
    const int wm = (warp & 1) * 64, wn = (warp >> 1) * 32;
    const int am = (warp & 1) * 4, bn = (warp >> 1) * 4;
    const int n0 = blockIdx.x * 128;
    const size_t mb0 = (size_t)blockIdx.y * 8;
    const size_t nb0 = (size_t)(n0 >> 3);
    if (tid < 128) sbias[tid] = b1[n0 + tid];
    __syncthreads();
    const unsigned sb = sptr(dsm);
    const int NTk = DD / 32;

#define ISS1(kt, st) do {                                                       \
        const unsigned ab = sb + (st) * STGB;                                   \
        const unsigned bb = ab + ASTG;                                          \
        const size_t kb0 = (size_t)(kt) * 2;                                    \
        _Pragma("unroll")                                                       \
        for (int l = 0; l < 2; l++) {                                           \
            int c = tid + l * 256;                                              \
            int mb = c >> 6, kb = (c >> 5) & 1, ln = c & 31;                    \
            CPA16(ab + c * 16,                                                  \
                  g_aF16 + (((mb0 + mb) * 64 + kb0 + kb) * 32 + ln) * 4);       \
        }                                                                       \
        _Pragma("unroll")                                                       \
        for (int l = 0; l < 2; l++) {                                           \
            int c = tid + l * 256;                                              \
            int nb = c >> 5, rm = c & 31, kb = rm >> 4, ch = rm & 15;           \
            CPA16(bb + c * 16,                                                  \
                  g_w1F16 + (((nb0 + nb) * 64 + kb0 + kb) * 32 + ch * 2) * 2);  \
        }                                                                       \
        CPA_COMMIT();                                                           \
    } while (0)

    float acc[4][4][4];
#pragma unroll
    for (int mi = 0; mi < 4; mi++)
#pragma unroll
        for (int ni = 0; ni < 4; ni++)
#pragma unroll
            for (int r = 0; r < 4; r++) acc[mi][ni][r] = 0.f;

    uint4 af[2][4]; uint2 bf[2][4];

    ISS1(0, 0); ISS1(1, 1);
    for (int kt = 0; kt < NTk; kt++) {
        if (kt + 1 < NTk) { CPA_WAIT1(); } else { CPA_WAIT0(); }
        __syncthreads();
        const unsigned char* stg = dsm + (kt % NSTAGE) * STGB;
        LOADF(0, 0);
        if (kt + 2 < NTk) ISS1(kt + 2, (kt + 2) % NSTAGE);
        LOADF(1, 1);
        MMAS(0);
        MMAS(1);
        __syncthreads();
    }
    __half* Ts = (__half*)dsm;
#pragma unroll
    for (int mi = 0; mi < 4; mi++) {
        const int row = wm + mi * 16 + gid;
#pragma unroll
        for (int ni = 0; ni < 4; ni++) {
            const int col = wn + ni * 8 + 2 * tg;
            Ts[col * 132 + row]           = __float2half_rn(fmaxf(acc[mi][ni][0] + sbias[col], 0.f));
            Ts[(col + 1) * 132 + row]     = __float2half_rn(fmaxf(acc[mi][ni][1] + sbias[col + 1], 0.f));
            Ts[col * 132 + row + 8]       = __float2half_rn(fmaxf(acc[mi][ni][2] + sbias[col], 0.f));
            Ts[(col + 1) * 132 + row + 8] = __float2half_rn(fmaxf(acc[mi][ni][3] + sbias[col + 1], 0.f));
        }
    }
    __syncthreads();
#pragma unroll
    for (int i = 0; i < 8; i++) {
        const int col = i * 16 + 2 * tg;
        const int row = warp * 16 + gid;
        uint4 o;
        o.x = pkh(Ts[col * 132 + row],           Ts[(col + 1) * 132 + row]);
        o.y = pkh(Ts[col * 132 + row + 8],       Ts[(col + 1) * 132 + row + 8]);
        o.z = pkh(Ts[(col + 8) * 132 + row],     Ts[(col + 9) * 132 + row]);
        o.w = pkh(Ts[(col + 8) * 132 + row + 8], Ts[(col + 9) * 132 + row + 8]);
        *(uint4*)(g_actF16 + (((mb0 + warp) * 128 + (n0 >> 4) + i) * 32 + lane) * 4) = o;
    }
#undef ISS1
}

// ---------------- gemm2: g_x = act @ W2 + b2 + embed[seq] ----------------
__global__ __launch_bounds__(256) void gemm2_kernel(const int* __restrict__ seq,
                                                    const float* __restrict__ embed,
                                                    const float* __restrict__ b2) {
    extern __shared__ unsigned char dsm[];
    __shared__ float sbias[128];
    __shared__ int srow[128];
    const int tid = threadIdx.x, warp = tid >> 5, lane = tid & 31;
    const int gid = lane >> 2, tg = lane & 3;
    const int wm = (warp & 1) * 64, wn = (warp >> 1) * 32;
    const int am = (warp & 1) * 4, bn = (warp >> 1) * 4;
    const int n0 = blockIdx.x * 128;
    const int row0 = blockIdx.y * 128;
    const size_t mb0 = (size_t)blockIdx.y * 8;
    const size_t nb0 = (size_t)(n0 >> 3);
    if (tid < 128) { sbias[tid] = b2[n0 + tid]; srow[tid] = seq[row0 + tid] * DD; }
    __syncthreads();
    const unsigned sb = sptr(dsm);
    const int NTk = H2 / 32;

#define ISS2(kt, st) do {                                                       \
        const unsigned ab = sb + (st) * STGB;                                   \
        const unsigned bb = ab + ASTG;                                          \
        const size_t kb0 = (size_t)(kt) * 2;                                    \
        _Pragma("unroll")                                                       \
        for (int l = 0; l < 2; l++) {                                           \
            int c = tid + l * 256;                                              \
            int mb = c >> 6, kb = (c >> 5) & 1, ln = c & 31;                    \
            CPA16(ab + c * 16,                                                  \
                  g_actF16 + (((mb0 + mb) * 128 + kb0 + kb) * 32 + ln) * 4);    \
        }                                                                       \
        _Pragma("unroll")                                                       \
        for (int l = 0; l < 2; l++) {                                           \
            int c = tid + l * 256;                                              \
            int nb = c >> 5, rm = c & 31, kb = rm >> 4, ch = rm & 15;           \
            CPA16(bb + c * 16,                                                  \
                  g_w2F16 + (((nb0 + nb) * 128 + kb0 + kb) * 32 + ch * 2) * 2); \
        }                                                                       \
        CPA_COMMIT();                                                           \
    } while (0)

    float acc[4][4][4];
#pragma unroll
    for (int mi = 0; mi < 4; mi++)
#pragma unroll
        for (int ni = 0; ni < 4; ni++)
#pragma unroll
            for (int r = 0; r < 4; r++) acc[mi][ni][r] = 0.f;

    uint4 af[2][4]; uint2 bf[2][4];

    ISS2(0, 0); ISS2(1, 1);
    for (int kt = 0; kt < NTk; kt++) {
        if (kt + 1 < NTk) { CPA_WAIT1(); } else { CPA_WAIT0(); }
        __syncthreads();
        const unsigned char* stg = dsm + (kt % NSTAGE) * STGB;
        LOADF(0, 0);
        if (kt + 2 < NTk) ISS2(kt + 2, (kt + 2) % NSTAGE);
        LOADF(1, 1);
        MMAS(0);
        MMAS(1);
        __syncthreads();
    }
    float* Tf = (float*)dsm;
#pragma unroll
    for (int mi = 0; mi < 4; mi++) {
        const int row = wm + mi * 16 + gid;
#pragma unroll
        for (int ni = 0; ni < 4; ni++) {
            const int col = wn + ni * 8 + 2 * tg;
            Tf[col * 132 + row]           = acc[mi][ni][0] + sbias[col];
            Tf[(col + 1) * 132 + row]     = acc[mi][ni][1] + sbias[col + 1];
            Tf[col * 132 + row + 8]       = acc[mi][ni][2] + sbias[col];
            Tf[(col + 1) * 132 + row + 8] = acc[mi][ni][3] + sbias[col + 1];
        }
    }
    __syncthreads();
    {
        const int rr = tid >> 1, half = (tid & 1) * 64;
        const size_t gr = (size_t)(row0 + rr) * DD + n0;
        const float* ep = embed + (size_t)srow[rr] + n0;
#pragma unroll
        for (int j = 0; j < 16; j++) {
            const int c0 = half + j * 4;
            float4 e = *(const float4*)(ep + c0);
            float4 o;
            o.x = Tf[(c0 + 0) * 132 + rr] + e.x;
            o.y = Tf[(c0 + 1) * 132 + rr] + e.y;
            o.z = Tf[(c0 + 2) * 132 + rr] + e.z;
            o.w = Tf[(c0 + 3) * 132 + rr] + e.w;
            *(float4*)(g_x + gr + c0) = o;
        }
    }
#undef ISS2
}

// ---------------- K3: LayerNorm + slot_imp + query extraction ----------------
__global__ __launch_bounds__(256) void ln_kernel(
    const float* __restrict__ ln_g, const float* __restrict__ ln_b) {
    const int token = blockIdx.x;
    const int tid = threadIdx.x;
    const float4 x4 = *(const float4*)(g_x + (size_t)token * DD + tid * 4);
    float s = x4.x + x4.y + x4.z + x4.w;
    float sq = x4.x * x4.x + x4.y * x4.y + x4.z * x4.z + x4.w * x4.w;
    __shared__ float sh1[8], sh2[8];
    const int w = tid >> 5, l = tid & 31;
    s = warp_sum(s);
    sq = warp_sum(sq);
    if (l == 0) { sh1[w] = s; sh2[w] = sq; }
    __syncthreads();
    float ts = 0.f, tq = 0.f;
#pragma unroll
    for (int i = 0; i < 8; i++) { ts += sh1[i]; tq += sh2[i]; }
    const float mu = ts * (1.f / 1024.f);
    const float var = tq * (1.f / 1024.f) - mu * mu;
    const float rstd = rsqrtf(var + 1e-5f);
    const float4 g4 = *(const float4*)(ln_g + tid * 4);
    const float4 b4 = *(const float4*)(ln_b + tid * 4);
    float4 h4;
    h4.x = (x4.x - mu) * rstd * g4.x + b4.x;
    h4.y = (x4.y - mu) * rstd * g4.y + b4.y;
    h4.z = (x4.z - mu) * rstd * g4.z + b4.z;
    h4.w = (x4.w - mu) * rstd * g4.w + b4.w;
    *(float4*)(g_hidden + (size_t)token * DD + tid * 4) = h4;
    const float4 wb = *(const float4*)(g_wbar + tid * 4);
    float wd = h4.x * wb.x + h4.y * wb.y + h4.z * wb.z + h4.w * wb.w;
    wd = warp_sum(wd);
    __syncthreads();
    if (l == 0) sh1[w] = wd;
    __syncthreads();
    if (tid == 0) {
        float t2 = 0.f;
#pragma unroll
        for (int i = 0; i < 8; i++) t2 += sh1[i];
        g_slot[token] = t2;   // constant offset (mean wg_b) omitted: rank-invariant
    }
    if ((token & (TT - 1)) == TT - 1) {
        int bidx = token >> 9;
        *(float4*)(g_query + bidx * DD + tid * 4) = h4;
    }
}

// ---------------- K4: top-k selection + memory assembly ----------------
__global__ __launch_bounds__(256) void select_kernel(const float* __restrict__ memory) {
    const int b = blockIdx.x, tid = threadIdx.x;
    __shared__ float imp[512];
    __shared__ int idx[6];
    for (int t = tid; t < TT - 1; t += 256) imp[t] = g_slot[b * TT + t];
    __syncthreads();
    if (tid == 0) {
#pragma unroll
        for (int r = 0; r < 4; r++) {       // fwd top-4 (desc, stable)
            float best = -1e30f; int bi = 0;
            for (int t = 0; t < TT - 1; t++)
                if (imp[t] > best) { best = imp[t]; bi = t; }
            idx[r] = bi;
            imp[bi] = -3.0e38f;
        }
#pragma unroll
        for (int r = 0; r < 2; r++) {       // rev top-2 over first 8, masked
            float best = -1e30f; int bi = 0;
            for (int t = 0; t < 8; t++)
                if (imp[t] > best) { best = imp[t]; bi = t; }
            idx[4 + r] = bi;
            imp[bi] = -3.0e38f;
        }
    }
    __syncthreads();
    for (int s = 0; s < SS; s++) {
        const float* src = (s < 6)
            ? (g_hidden + (size_t)(b * TT + idx[s]) * DD)
            : (memory + (size_t)s * DD);
        *(float4*)(g_mem + (size_t)(b * SS + s) * DD + tid * 4) =
            *(const float4*)(src + tid * 4);
    }
}

// ---------------- K7: q = query @ rp_w + rp_b ----------------
__global__ __launch_bounds__(256) void rp_kernel(
    const float* __restrict__ rp_w, const float* __restrict__ rp_b) {
    const int b = blockIdx.x, tid = threadIdx.x;
    __shared__ __align__(16) float qs[DD];
    *(float4*)&qs[tid * 4] = *(const float4*)(g_query + b * DD + tid * 4);
    __syncthreads();
    float acc0 = 0.f, acc1 = 0.f, acc2 = 0.f, acc3 = 0.f;
    for (int d = 0; d < DD; d++) {
        const float q = qs[d];
        const float* wr = rp_w + (size_t)d * DD + tid;
        acc0 += q * wr[0];
        acc1 += q * wr[256];
        acc2 += q * wr[512];
        acc3 += q * wr[768];
    }
    g_q[b * DD + tid +   0] = acc0 + rp_b[tid +   0];
    g_q[b * DD + tid + 256] = acc1 + rp_b[tid + 256];
    g_q[b * DD + tid + 512] = acc2 + rp_b[tid + 512];
    g_q[b * DD + tid + 768] = acc3 + rp_b[tid + 768];
}

// ---------------- K8: scores -> softmax -> PURE ctxattn (no blend) ----------------
__global__ __launch_bounds__(256) void attn_kernel() {
    const int b = blockIdx.x, tid = threadIdx.x;
    __shared__ __align__(16) float qs[DD];
    __shared__ float sh[8];
    __shared__ float scores[SS];
    __shared__ float attn[SS];
    *(float4*)&qs[tid * 4] = *(const float4*)(g_q + b * DD + tid * 4);
    __syncthreads();
    for (int s = 0; s < SS; s++) {
        const float4 m4 = *(const float4*)(g_mem + (size_t)(b * SS + s) * DD + tid * 4);
        const float4 q4 = *(const float4*)&qs[tid * 4];
        float p = m4.x * q4.x + m4.y * q4.y + m4.z * q4.z + m4.w * q4.w;
        p = warp_sum(p);
        if ((tid & 31) == 0) sh[tid >> 5] = p;
        __syncthreads();
        if (tid == 0) {
            float t = 0.f;
#pragma unroll
            for (int i = 0; i < 8; i++) t += sh[i];
            scores[s] = t;
        }
        __syncthreads();
    }
    if (tid == 0) {
        float m = scores[0];
        for (int s = 1; s < SS; s++) m = fmaxf(m, scores[s]);
        float sum = 0.f;
        for (int s = 0; s < SS; s++) { float e = expf(scores[s] - m); attn[s] = e; sum += e; }
        const float inv = 1.f / sum;
        for (int s = 0; s < SS; s++) attn[s] *= inv;
    }
    __syncthreads();
    float c0 = 0.f, c1 = 0.f, c2 = 0.f, c3 = 0.f;
#pragma unroll
    for (int s = 0; s < SS; s++) {
        const float a = attn[s];
        const float4 m4 = *(const float4*)(g_mem + (size_t)(b * SS + s) * DD + tid * 4);
        c0 += a * m4.x; c1 += a * m4.y; c2 += a * m4.z; c3 += a * m4.w;
    }
    float4 o;
    o.x = c0; o.y = c1; o.z = c2; o.w = c3;
    *(float4*)(g_ctx + b * DD + tid * 4) = o;
}

// ---------------- fused vocab GEMM (tf32 mma, M=64): one pass over out_w ----------------
// rows 0-31: g_query -> g_dl ; rows 32-63: g_ctx (pure ctxattn) -> g_cl
// Tail: v0 clamped to VOCAB-128; overlap cols written twice with identical values.
__global__ __launch_bounds__(256) void vlogits_kernel(
    const float* __restrict__ W, const float* __restrict__ bias) {
    extern __shared__ unsigned vsm[];
    unsigned* As = vsm;                      // [2][VASZ]
    unsigned* Bs = vsm + 2 * VASZ;           // [2][VBSZ]
    const int tid = threadIdx.x, warp = tid >> 5, lane = tid & 31;
    const int gid = lane >> 2, tg = lane & 3;
    const int wn = warp * 16;
    int v0 = blockIdx.x * 128;
    if (v0 > VOCAB - 128) v0 = VOCAB - 128;

    const int ar = tid >> 2;                 // 64 rows
    const int akq = (tid & 3) * 2;           // 2 float4 quads per thread
    const float* arow = (ar < 32) ? (g_query + ar * DD) : (g_ctx + (ar - 32) * DD);
    const int bkr = warp, bc4 = lane * 4;

    float4 aR0, aR1;
    float bR[16];

#define CLQ_LOAD(kt) do {                                                       \
        const int k0q = (kt) * 32;                                              \
        aR0 = *(const float4*)(arow + k0q + akq * 4);                           \
        aR1 = *(const float4*)(arow + k0q + akq * 4 + 4);                       \
        _Pragma("unroll")                                                       \
        for (int o = 0; o < 4; o++) {                                           \
            const float* wp = W + (size_t)(k0q + bkr + o * 8) * VOCAB + v0 + bc4; \
            bR[o * 4 + 0] = wp[0]; bR[o * 4 + 1] = wp[1];                       \
            bR[o * 4 + 2] = wp[2]; bR[o * 4 + 3] = wp[3];                       \
        }                                                                       \
    } while (0)
#define CLQ_STORE(buf) do {                                                     \
        unsigned* Ad = As + (buf) * VASZ; unsigned* Bd = Bs + (buf) * VBSZ;     \
        uint4 t0, t1;                                                           \
        t0.x = __float_as_uint(aR0.x); t0.y = __float_as_uint(aR0.y);           \
        t0.z = __float_as_uint(aR0.z); t0.w = __float_as_uint(aR0.w);           \
        t1.x = __float_as_uint(aR1.x); t1.y = __float_as_uint(aR1.y);           \
        t1.z = __float_as_uint(aR1.z); t1.w = __float_as_uint(aR1.w);           \
        *(uint4*)&Ad[ar * APAD + akq * 4] = t0;                                 \
        *(uint4*)&Ad[ar * APAD + akq * 4 + 4] = t1;                             \
        _Pragma("unroll")                                                       \
        for (int o = 0; o < 4; o++) {                                           \
            uint4 tb;                                                           \
            tb.x = __float_as_uint(bR[o * 4 + 0]);                              \
            tb.y = __float_as_uint(bR[o * 4 + 1]);                              \
            tb.z = __float_as_uint(bR[o * 4 + 2]);                              \
            tb.w = __float_as_uint(bR[o * 4 + 3]);                              \
            *(uint4*)&Bd[(bkr + o * 8) * BPAD + bc4] = tb;                      \
        }                                                                       \
    } while (0)

    float acc[4][2][4];
#pragma unroll
    for (int mi = 0; mi < 4; mi++)
#pragma unroll
        for (int ni = 0; ni < 2; ni++)
#pragma unroll
            for (int r = 0; r < 4; r++) acc[mi][ni][r] = 0.f;

    CLQ_LOAD(0);
    CLQ_STORE(0);
    for (int kt = 0; kt < 32; kt++) {
        __syncthreads();
        if (kt + 1 < 32) CLQ_LOAD(kt + 1);
        const unsigned* Ab = As + (kt & 1) * VASZ;
        const unsigned* Bb = Bs + (kt & 1) * VBSZ;
#pragma unroll
        for (int ks = 0; ks < 32; ks += 8) {
            unsigned a[4][4], b[2][2];
#pragma unroll
            for (int mi = 0; mi < 4; mi++) {
                int mb = (mi * 16 + gid) * APAD;
                a[mi][0] = f2tf(__uint_as_float(Ab[mb + ks + tg]));
                a[mi][1] = f2tf(__uint_as_float(Ab[mb + 8 * APAD + ks + tg]));
                a[mi][2] = f2tf(__uint_as_float(Ab[mb + ks + tg + 4]));
                a[mi][3] = f2tf(__uint_as_float(Ab[mb + 8 * APAD + ks + tg + 4]));
            }
#pragma unroll
            for (int ni = 0; ni < 2; ni++) {
                int c = wn + ni * 8 + gid;
                b[ni][0] = f2tf(__uint_as_float(Bb[(ks + tg) * BPAD + c]));
                b[ni][1] = f2tf(__uint_as_float(Bb[(ks + tg + 4) * BPAD + c]));
            }
#pragma unroll
            for (int mi = 0; mi < 4; mi++)
#pragma unroll
                for (int ni = 0; ni < 2; ni++)
                    mma_tf32(acc[mi][ni], a[mi][0], a[mi][1], a[mi][2], a[mi][3],
                             b[ni][0], b[ni][1]);
        }
        if (kt + 1 < 32) CLQ_STORE((kt + 1) & 1);
    }
#pragma unroll
    for (int mi = 0; mi < 4; mi++) {
        const int m = mi * 16 + gid;                 // 0..63 (rows m, m+8 same half)
        float* dst = (mi < 2) ? g_dl : g_cl;
        const int rm = m & 31;
#pragma unroll
        for (int ni = 0; ni < 2; ni++) {
            int vc = v0 + wn + ni * 8 + 2 * tg;
            float bi0 = bias[vc], bi1 = bias[vc + 1];
            dst[(size_t)rm * VOCAB + vc]           = acc[mi][ni][0] + bi0;
            dst[(size_t)rm * VOCAB + vc + 1]       = acc[mi][ni][1] + bi1;
            dst[(size_t)(rm + 8) * VOCAB + vc]     = acc[mi][ni][2] + bi0;
            dst[(size_t)(rm + 8) * VOCAB + vc + 1] = acc[mi][ni][3] + bi1;
        }
    }
#undef CLQ_LOAD
#undef CLQ_STORE
}

// ---------------- K6: conf = 1/sumexp(dl - max) -> use_mem flag ----------------
__global__ __launch_bounds__(256) void conf_kernel() {
    const int b = blockIdx.x, tid = threadIdx.x;
    const float* row = g_dl + (size_t)b * VOCAB;
    float m = -3.0e38f;
    for (int v = tid; v < VOCAB; v += 256) m = fmaxf(m, row[v]);
    __shared__ float sh[8];
#pragma unroll
    for (int o = 16; o > 0; o >>= 1) m = fmaxf(m, __shfl_xor_sync(0xffffffffu, m, o));
    if ((tid & 31) == 0) sh[tid >> 5] = m;
    __syncthreads();
    float bm = sh[0];
#pragma unroll
    for (int i = 1; i < 8; i++) bm = fmaxf(bm, sh[i]);
    float ssum = 0.f;
    for (int v = tid; v < VOCAB; v += 256) ssum += expf(row[v] - bm);
    ssum = warp_sum(ssum);
    __syncthreads();
    if ((tid & 31) == 0) sh[tid >> 5] = ssum;
    __syncthreads();
    if (tid == 0) {
        float t = 0.f;
#pragma unroll
        for (int i = 0; i < 8; i++) t += sh[i];
        const float conf = 1.f / t;
        g_use[b] = (conf < 0.8f) ? 1.f : 0.f;
    }
}

// ---------------- K9: output select (use is exactly 0/1 -> bitwise select) ----------------
// NOTE: VOCAB is odd, so row bases are only 4B-aligned -> SCALAR accesses only.
__global__ __launch_bounds__(256) void blend_kernel(float* __restrict__ out) {
    const int b = blockIdx.y;
    const int v = blockIdx.x * 1024 + threadIdx.x;   // 4 strided scalars per thread
    const bool um = (g_use[b] != 0.f);
    const size_t base = (size_t)b * VOCAB;
    const float* src = um ? g_cl : g_dl;
#pragma unroll
    for (int j = 0; j < 4; j++) {
        int vv = v + j * 256;
        if (vv < VOCAB) out[base + vv] = src[base + vv];
    }
}

// ---------------- launch ----------------
extern "C" void kernel_launch(void* const* d_in, const int* in_sizes, int n_in,
                              void* d_out, int out_size) {
    const int*   seq    = (const int*)  d_in[0];
    const float* embed  = (const float*)d_in[1];
    const float* ff_w1  = (const float*)d_in[2];
    const float* ff_b1  = (const float*)d_in[3];
    const float* ff_w2  = (const float*)d_in[4];
    const float* ff_b2  = (const float*)d_in[5];
    const float* ln_g   = (const float*)d_in[6];
    const float* ln_b   = (const float*)d_in[7];
    const float* wg_w   = (const float*)d_in[8];
    // d_in[9] = wg_b: constant shift of slot_imp, rank-invariant -> unused
    const float* rp_w   = (const float*)d_in[10];
    const float* rp_b   = (const float*)d_in[11];
    const float* out_w  = (const float*)d_in[12];
    const float* out_b  = (const float*)d_in[13];
    const float* memory = (const float*)d_in[14];
    float* out = (float*)d_out;

    cudaFuncSetAttribute(gemm1_kernel, cudaFuncAttributeMaxDynamicSharedMemorySize, GSMEM_G);
    cudaFuncSetAttribute(gemm2_kernel, cudaFuncAttributeMaxDynamicSharedMemorySize, GSMEM_G);
    cudaFuncSetAttribute(vlogits_kernel, cudaFuncAttributeMaxDynamicSharedMemorySize, GSMEM_V);

    wbar_kernel<<<4, 256>>>(wg_w);
    prep_w1<<<(H2 / 8) * (DD / 16) * 32 / 256, 256>>>(ff_w1);
    prep_w2<<<(DD / 8) * (H2 / 16) * 32 / 256, 256>>>(ff_w2);
    prep_a<<<BT / 16, 256, 16 * PADW * 2>>>(seq, embed);
    gemm1_kernel<<<dim3(H2 / 128, BT / 128), 256, GSMEM_G>>>(ff_b1);
    gemm2_kernel<<<dim3(DD / 128, BT / 128), 256, GSMEM_G>>>(seq, embed, ff_b2);
    ln_kernel<<<BT, 256>>>(ln_g, ln_b);
    select_kernel<<<BB, 256>>>(memory);
    rp_kernel<<<BB, 256>>>(rp_w, rp_b);
    attn_kernel<<<BB, 256>>>();
    vlogits_kernel<<<(VOCAB + 127) / 128, 256, GSMEM_V>>>(out_w, out_b);
    conf_kernel<<<BB, 256>>>();
    blend_kernel<<<dim3((VOCAB + 1023) / 1024, BB), 256>>>(out);
}